// round 6
// baseline (speedup 1.0000x reference)
#include <cuda_runtime.h>
#include <math_constants.h>

#define BATCH 8
#define HH 224
#define WW 224
#define OH 223
#define OW 223
#define TBX 4            // 4x4 tiles per batch
#define NBLK (TBX * TBX) // 16 blocks per batch
#define TILE 56          // output tile 56x56
#define HALO 57          // input halo tile 57x57
#define NPIX (HALO * HALO)   // 3249
#define NV4  1568        // 25088 float4 per batch / 16 blocks
#define PI_F 3.14159265358979323846f

// Per-(batch,block) min/max partials — each block owns its slot, written
// unconditionally every launch (no reset needed, graph-replay safe).
__device__ float g_pmin[BATCH][NBLK];
__device__ float g_pmax[BATCH][NBLK];
// Monotonic ticket counter per batch (never reset; wrap-safe signed compare).
__device__ unsigned g_cnt[BATCH];

static __device__ __forceinline__ unsigned ldcg_u32(const unsigned* p) {
    unsigned v;
    asm volatile("ld.global.cg.u32 %0, [%1];" : "=r"(v) : "l"(p) : "memory");
    return v;
}

__global__ void __launch_bounds__(1024)
quanv_fused(const float* __restrict__ x, const float* __restrict__ wts,
            float* __restrict__ out) {
    __shared__ float sT[NPIX];
    __shared__ float sS[NPIX];
    __shared__ float sred[64];           // 32 warp mins + 32 warp maxs
    __shared__ float s_fmn, s_scale;
    __shared__ float s_cw[4], s_sw[4];

    const int b   = blockIdx.z;
    const int blk = blockIdx.y * TBX + blockIdx.x;   // 0..15
    const int tid = threadIdx.x;
    const int r0  = blockIdx.y * TILE;
    const int c0  = blockIdx.x * TILE;

    if (tid < 4) {
        float w = wts[tid];
        s_cw[tid] = cosf(w);
        s_sw[tid] = sinf(w);
    }

    // ---- Phase 1: local min/max over this block's 1/16 slice of the batch ----
    const float* xb = x + (size_t)b * 2 * HH * WW;
    const float4* xv = (const float4*)xb + blk * NV4;
    float lmin = CUDART_INF_F, lmax = -CUDART_INF_F;
    #pragma unroll
    for (int j = 0; j < 2; j++) {                    // 1568 = 1024 + 544
        int i = j * 1024 + tid;
        if (i < NV4) {
            float4 v = xv[i];
            lmin = fminf(lmin, fminf(fminf(v.x, v.y), fminf(v.z, v.w)));
            lmax = fmaxf(lmax, fmaxf(fmaxf(v.x, v.y), fmaxf(v.z, v.w)));
        }
    }
    #pragma unroll
    for (int off = 16; off > 0; off >>= 1) {
        lmin = fminf(lmin, __shfl_xor_sync(0xFFFFFFFFu, lmin, off));
        lmax = fmaxf(lmax, __shfl_xor_sync(0xFFFFFFFFu, lmax, off));
    }
    if ((tid & 31) == 0) { sred[tid >> 5] = lmin; sred[32 + (tid >> 5)] = lmax; }

    // ---- Prefetch raw halo tile pixels (latency hides behind barrier wait) ----
    const float* x0 = xb;
    const float* x1 = xb + HH * WW;
    float ra[4], rb[4];
    #pragma unroll
    for (int j = 0; j < 4; j++) {
        int i = tid + j * 1024;
        if (i < NPIX) {
            int rr = i / HALO, cc = i - rr * HALO;
            int r = min(r0 + rr, HH - 1);
            int c = min(c0 + cc, WW - 1);
            ra[j] = __ldg(x0 + r * WW + c);
            rb[j] = __ldg(x1 + r * WW + c);
        }
    }

    __syncthreads();

    // ---- Publish partial + arrive (atomic), wait by plain L2 loads ----
    if (tid == 0) {
        float m0 = sred[0], m1 = sred[32];
        #pragma unroll
        for (int i = 1; i < 32; i++) {
            m0 = fminf(m0, sred[i]);
            m1 = fmaxf(m1, sred[32 + i]);
        }
        __stcg(&g_pmin[b][blk], m0);
        __stcg(&g_pmax[b][blk], m1);
        __threadfence();                               // partials visible before arrive
        unsigned ticket = atomicAdd(&g_cnt[b], 1u);
        unsigned target = ticket - (ticket % NBLK) + NBLK;
        while ((int)(ldcg_u32(&g_cnt[b]) - target) < 0) { }
        __threadfence();                               // acquire
    }
    __syncthreads();

    // ---- Reduce the 16 partials (first warp) ----
    if (tid < 32) {
        float pm = CUDART_INF_F, px = -CUDART_INF_F;
        if (tid < NBLK) {
            pm = __ldcg(&g_pmin[b][tid]);
            px = __ldcg(&g_pmax[b][tid]);
        }
        #pragma unroll
        for (int off = 8; off > 0; off >>= 1) {
            pm = fminf(pm, __shfl_xor_sync(0xFFFFFFFFu, pm, off));
            px = fmaxf(px, __shfl_xor_sync(0xFFFFFFFFu, px, off));
        }
        if (tid == 0) {
            s_fmn = pm;
            s_scale = PI_F / (px - pm + 1e-8f);
        }
    }
    __syncthreads();

    // ---- Transform tile: t = cos(a)cos(b), s = sin(a) ----
    const float fmn = s_fmn, scale = s_scale;
    #pragma unroll
    for (int j = 0; j < 4; j++) {
        int i = tid + j * 1024;
        if (i < NPIX) {
            float a  = (ra[j] - fmn) * scale;
            float bb = (rb[j] - fmn) * scale;
            float sa, ca;
            __sincosf(a, &sa, &ca);
            sT[i] = ca * __cosf(bb);
            sS[i] = sa;
        }
    }
    __syncthreads();

    // ---- Output: z_i = cw_i*t - sw_i*s at 4 corners, parity products ----
    const float cw0 = s_cw[0], sw0 = s_sw[0];
    const float cw1 = s_cw[1], sw1 = s_sw[1];
    const float cw2 = s_cw[2], sw2 = s_sw[2];
    const float cw3 = s_cw[3], sw3 = s_sw[3];

    const size_t plane = (size_t)OH * OW;
    float* ob = out + (size_t)b * 4 * plane;

    #pragma unroll
    for (int k = 0; k < 4; k++) {
        int idx = tid + k * 1024;                      // 0..3135 over 56x56
        if (idx < TILE * TILE) {
            int ly = idx / TILE, lx = idx - ly * TILE;
            int oh = r0 + ly;
            int ow = c0 + lx;
            if (oh < OH && ow < OW) {
                int p = ly * HALO + lx;
                float z0 = fmaf(cw0, sT[p],            -sw0 * sS[p]);
                float z1 = fmaf(cw1, sT[p + 1],        -sw1 * sS[p + 1]);
                float z2 = fmaf(cw2, sT[p + HALO],     -sw2 * sS[p + HALO]);
                float z3 = fmaf(cw3, sT[p + HALO + 1], -sw3 * sS[p + HALO + 1]);
                float z01 = z0 * z1;
                float z23 = z2 * z3;
                size_t o = (size_t)oh * OW + ow;
                ob[0 * plane + o] = z1 * z23;   // <Z0> = z1 z2 z3
                ob[1 * plane + o] = z01;        // <Z1> = z0 z1
                ob[2 * plane + o] = z01 * z2;   // <Z2> = z0 z1 z2
                ob[3 * plane + o] = z01 * z23;  // <Z3> = z0 z1 z2 z3
            }
        }
    }
}

extern "C" void kernel_launch(void* const* d_in, const int* in_sizes, int n_in,
                              void* d_out, int out_size) {
    const float* x   = (const float*)d_in[0];   // [8,2,224,224]
    const float* wts = (const float*)d_in[1];   // [1,4]
    float* out = (float*)d_out;                 // [8,4,223,223]

    dim3 grid(TBX, TBX, BATCH);                 // 128 blocks, 1 per SM
    quanv_fused<<<grid, 1024>>>(x, wts, out);
}

// round 9
// speedup vs baseline: 1.2362x; 1.2362x over previous
#include <cuda_runtime.h>
#include <math_constants.h>

#define BATCH 8
#define HH 224
#define WW 224
#define OH 223
#define OW 223
#define TBX 4
#define NBLK (TBX * TBX)     // 16 CTAs per batch
#define TILE 56
#define HALO 57
#define NPIX (HALO * HALO)   // 3249
#define PI_F 3.14159265358979323846f

// Per-(batch,block) min/max partials — block-owned slots, written every launch.
__device__ float g_pmin[BATCH][NBLK];
__device__ float g_pmax[BATCH][NBLK];
// Monotonic ticket counter per batch (never reset; wrap-safe signed compare).
__device__ unsigned g_cnt[BATCH];

static __device__ __forceinline__ unsigned ldcg_u32(const unsigned* p) {
    unsigned v;
    asm volatile("ld.global.cg.u32 %0, [%1];" : "=r"(v) : "l"(p) : "memory");
    return v;
}

__global__ void __launch_bounds__(256)
quanv_fused(const float* __restrict__ x, const float* __restrict__ wts,
            float* __restrict__ out) {
    __shared__ float sT[NPIX];
    __shared__ float sS[NPIX];
    __shared__ float sred[16];           // 8 warp mins + 8 warp maxs
    __shared__ float s_rm[2];
    __shared__ float s_cw[4], s_sw[4];

    const int b   = blockIdx.z;
    const int blk = blockIdx.y * TBX + blockIdx.x;   // 0..15
    const int tid = threadIdx.x;
    const int r0  = blockIdx.y * TILE;
    const int c0  = blockIdx.x * TILE;

    if (tid < 4) {
        float w = wts[tid];
        s_cw[tid] = cosf(w);
        s_sw[tid] = sinf(w);
    }

    const float* x0 = x + (size_t)b * 2 * HH * WW;
    const float* x1 = x0 + HH * WW;

    // ---- Single read phase: halo pixels -> registers; min/max on the fly ----
    // The 16 halos tile the whole batch (with overlap), so min/max over the
    // union of halo pixels == min/max over the batch. One global read total.
    float ra[13], rb[13];
    float lmin = CUDART_INF_F, lmax = -CUDART_INF_F;
    #pragma unroll
    for (int j = 0; j < 13; j++) {
        int i = tid + j * 256;
        if (i < NPIX) {
            int rr = i / HALO, cc = i - rr * HALO;
            int r = min(r0 + rr, HH - 1);
            int c = min(c0 + cc, WW - 1);
            float va = __ldg(x0 + r * WW + c);
            float vb = __ldg(x1 + r * WW + c);
            ra[j] = va; rb[j] = vb;
            lmin = fminf(lmin, fminf(va, vb));
            lmax = fmaxf(lmax, fmaxf(va, vb));
        }
    }
    #pragma unroll
    for (int off = 16; off > 0; off >>= 1) {
        lmin = fminf(lmin, __shfl_xor_sync(0xFFFFFFFFu, lmin, off));
        lmax = fmaxf(lmax, __shfl_xor_sync(0xFFFFFFFFu, lmax, off));
    }
    if ((tid & 31) == 0) { sred[tid >> 5] = lmin; sred[8 + (tid >> 5)] = lmax; }
    __syncthreads();

    // ---- Publish partial + arrive (atomic ticket), wait via plain L2 loads ----
    if (tid == 0) {
        float m0 = sred[0], m1 = sred[8];
        #pragma unroll
        for (int i = 1; i < 8; i++) {
            m0 = fminf(m0, sred[i]);
            m1 = fmaxf(m1, sred[8 + i]);
        }
        __stcg(&g_pmin[b][blk], m0);
        __stcg(&g_pmax[b][blk], m1);
        __threadfence();                               // partials visible before arrive
        unsigned ticket = atomicAdd(&g_cnt[b], 1u);
        unsigned target = ticket - (ticket % NBLK) + NBLK;
        while ((int)(ldcg_u32(&g_cnt[b]) - target) < 0) { }
        __threadfence();                               // acquire
    }
    __syncthreads();

    // ---- Reduce the 16 partials (first warp) ----
    if (tid < 32) {
        float pm = CUDART_INF_F, px = -CUDART_INF_F;
        if (tid < NBLK) {
            pm = __ldcg(&g_pmin[b][tid]);
            px = __ldcg(&g_pmax[b][tid]);
        }
        #pragma unroll
        for (int off = 8; off > 0; off >>= 1) {
            pm = fminf(pm, __shfl_xor_sync(0xFFFFFFFFu, pm, off));
            px = fmaxf(px, __shfl_xor_sync(0xFFFFFFFFu, px, off));
        }
        if (tid == 0) { s_rm[0] = pm; s_rm[1] = px; }
    }
    __syncthreads();

    const float fmn = s_rm[0];
    const float scale = PI_F / (s_rm[1] - fmn + 1e-8f);

    // ---- Transform registers -> smem: t = cos(a)cos(b), s = sin(a) ----
    #pragma unroll
    for (int j = 0; j < 13; j++) {
        int i = tid + j * 256;
        if (i < NPIX) {
            float a  = (ra[j] - fmn) * scale;
            float bb = (rb[j] - fmn) * scale;
            float sa, ca;
            __sincosf(a, &sa, &ca);
            sT[i] = ca * __cosf(bb);
            sS[i] = sa;
        }
    }
    __syncthreads();

    // ---- Output: z_i = cw_i*t - sw_i*s at 4 corners, parity products ----
    const float cw0 = s_cw[0], sw0 = s_sw[0];
    const float cw1 = s_cw[1], sw1 = s_sw[1];
    const float cw2 = s_cw[2], sw2 = s_sw[2];
    const float cw3 = s_cw[3], sw3 = s_sw[3];

    const size_t plane = (size_t)OH * OW;
    float* ob = out + (size_t)b * 4 * plane;

    #pragma unroll
    for (int k = 0; k < 13; k++) {
        int idx = tid + k * 256;                       // 0..3135 over 56x56
        if (idx < TILE * TILE) {
            int ly = idx / TILE, lx = idx - ly * TILE;
            int oh = r0 + ly;
            int ow = c0 + lx;
            if (oh < OH && ow < OW) {
                int p = ly * HALO + lx;
                float z0 = fmaf(cw0, sT[p],            -sw0 * sS[p]);
                float z1 = fmaf(cw1, sT[p + 1],        -sw1 * sS[p + 1]);
                float z2 = fmaf(cw2, sT[p + HALO],     -sw2 * sS[p + HALO]);
                float z3 = fmaf(cw3, sT[p + HALO + 1], -sw3 * sS[p + HALO + 1]);
                float z01 = z0 * z1;
                float z23 = z2 * z3;
                size_t o = (size_t)oh * OW + ow;
                ob[0 * plane + o] = z1 * z23;   // <Z0> = z1 z2 z3
                ob[1 * plane + o] = z01;        // <Z1> = z0 z1
                ob[2 * plane + o] = z01 * z2;   // <Z2> = z0 z1 z2
                ob[3 * plane + o] = z01 * z23;  // <Z3> = z0 z1 z2 z3
            }
        }
    }
}

extern "C" void kernel_launch(void* const* d_in, const int* in_sizes, int n_in,
                              void* d_out, int out_size) {
    const float* x   = (const float*)d_in[0];   // [8,2,224,224]
    const float* wts = (const float*)d_in[1];   // [1,4]
    float* out = (float*)d_out;                 // [8,4,223,223]

    dim3 grid(TBX, TBX, BATCH);                 // 128 CTAs x 256 thr = 32k threads
    quanv_fused<<<grid, 256>>>(x, wts, out);
}